// round 3
// baseline (speedup 1.0000x reference)
#include <cuda_runtime.h>
#include <math.h>

#define BB   2
#define CIN  16
#define CG   16      // channels per gate
#define NG   6
#define TT   31
#define HH   128
#define WW   128
#define HWSZ (HH*WW)
#define KV   27

// each thread computes 2 adjacent-w pixels; block covers 32w x 16h
#define TX   16      // threads in x (w-pairs)
#define TY   16      // threads in y (h)
#define BW   (TX*2)  // 32
#define BH   TY      // 16

// Scratch for activated gates: [gate][b][c][t][h][w]  (390 MB)
__device__ float g_gates[(size_t)NG * BB * CG * TT * HWSZ];

__device__ __forceinline__ void fma2(unsigned long long& d,
                                     unsigned long long a,
                                     unsigned long long b)
{
    asm("fma.rn.f32x2 %0, %1, %2, %0;" : "+l"(d) : "l"(a), "l"(b));
}

__device__ __forceinline__ unsigned long long pack2(float lo, float hi)
{
    unsigned long long r;
    asm("mov.b64 %0, {%1, %2};" : "=l"(r) : "f"(lo), "f"(hi));
    return r;
}

__device__ __forceinline__ unsigned long long dup2(float v)
{
    unsigned long long r;
    asm("mov.b64 %0, {%1, %1};" : "=l"(r) : "f"(v));
    return r;
}

__device__ __forceinline__ void unpack2(unsigned long long p, float& lo, float& hi)
{
    asm("mov.b64 {%0, %1}, %2;" : "=f"(lo), "=f"(hi) : "l"(p));
}

__global__ __launch_bounds__(256, 2)
void conv_gates_kernel(const float* __restrict__ x,
                       const float* __restrict__ cw,
                       const float* __restrict__ cb)
{
    // weights for this gate: [(ci*27 + j)*16 + oc]; oc-pairs are contiguous 8B
    __shared__ __align__(16) float w_s[CIN * KV * CG];       // 27648 B
    __shared__ float xs[3][BH + 2][BW + 2];                  // 3*18*34*4 = 7344 B

    const int tx  = threadIdx.x;                 // 0..15  (w-pair)
    const int ty  = threadIdx.y;                 // 0..15  (h)
    const int tid = ty * TX + tx;
    const int w0  = blockIdx.x * BW;
    const int h0  = blockIdx.y * BH;
    int z = blockIdx.z;
    const int t = z % TT; z /= TT;
    const int g = z % NG;
    const int b = z / NG;

    // stage weights for this gate's 16 output channels
    for (int i = tid; i < CIN * KV * CG; i += 256) {
        int oc = i & 15;
        int cj = i >> 4;                 // ci*27 + j
        w_s[i] = cw[(g * CG + oc) * (CIN * KV) + cj];
    }

    // accumulators: 8 oc-pairs per pixel, 2 pixels
    unsigned long long acc0[8], acc1[8];
#pragma unroll
    for (int q = 0; q < 8; q++) {
        unsigned long long bp = pack2(__ldg(&cb[g * CG + 2 * q]),
                                      __ldg(&cb[g * CG + 2 * q + 1]));
        acc0[q] = bp;
        acc1[q] = bp;
    }

    const float* xbase = x + (size_t)b * CIN * TT * HWSZ;

    for (int ci = 0; ci < CIN; ci++) {
        __syncthreads();   // protect previous iter's xs reads; fences w_s on iter 0
        // load x slice [3 t][BH+2][BW+2] with zero padding
        const float* xb = xbase + (size_t)ci * TT * HWSZ;
        for (int i = tid; i < 3 * (BH + 2) * (BW + 2); i += 256) {
            int dt  = i / ((BH + 2) * (BW + 2));
            int rem = i % ((BH + 2) * (BW + 2));
            int ih  = rem / (BW + 2);
            int iw  = rem % (BW + 2);
            int tg  = t - 1 + dt;
            int hh  = h0 - 1 + ih;
            int ww  = w0 - 1 + iw;
            float v = 0.0f;
            if (tg >= 0 && tg < TT && hh >= 0 && hh < HH && ww >= 0 && ww < WW)
                v = xb[(size_t)tg * HWSZ + hh * WW + ww];
            ((float*)xs)[i] = v;
        }
        __syncthreads();

        // union patch for the 2 adjacent-w pixels: [3][3][4]
        float xu[3][3][4];
#pragma unroll
        for (int dt = 0; dt < 3; dt++)
#pragma unroll
            for (int dh = 0; dh < 3; dh++)
#pragma unroll
                for (int dw = 0; dw < 4; dw++)
                    xu[dt][dh][dw] = xs[dt][ty + dh][2 * tx + dw];

#pragma unroll
        for (int dt = 0; dt < 3; dt++)
#pragma unroll
            for (int dh = 0; dh < 3; dh++)
#pragma unroll
                for (int dw = 0; dw < 3; dw++) {
                    const int j = (dt * 3 + dh) * 3 + dw;
                    unsigned long long xx0 = dup2(xu[dt][dh][dw]);
                    unsigned long long xx1 = dup2(xu[dt][dh][dw + 1]);
                    const ulonglong2* wq =
                        (const ulonglong2*)(w_s + (ci * KV + j) * CG);
#pragma unroll
                    for (int q = 0; q < 4; q++) {
                        ulonglong2 wv = wq[q];
                        fma2(acc0[2 * q],     xx0, wv.x);
                        fma2(acc0[2 * q + 1], xx0, wv.y);
                        fma2(acc1[2 * q],     xx1, wv.x);
                        fma2(acc1[2 * q + 1], xx1, wv.y);
                    }
                }
    }

    // activation + store (float2 per oc: the 2 adjacent-w pixels)
    const int hw = (h0 + ty) * WW + (w0 + 2 * tx);
    const bool use_tanh = (g == 0) || (g == 5);   // Wx, X -> tanh; others -> sigmoid
    float* gb = g_gates + (((size_t)g * BB + b) * CG * TT) * HWSZ + (size_t)t * HWSZ + hw;
#pragma unroll
    for (int q = 0; q < 8; q++) {
        float a0, a1, b0, b1;
        unpack2(acc0[q], a0, b0);   // oc=2q: pixel0 in lo? no: acc0 holds pixel0's pair
        unpack2(acc1[q], a1, b1);
        // acc0[q] = {oc=2q px0, oc=2q+1 px0}; acc1[q] = {oc=2q px1, oc=2q+1 px1}
        float v00 = a0, v10 = b0;   // pixel0: oc 2q, 2q+1
        float v01 = a1, v11 = b1;   // pixel1: oc 2q, 2q+1
        if (use_tanh) {
            v00 = tanhf(v00); v10 = tanhf(v10);
            v01 = tanhf(v01); v11 = tanhf(v11);
        } else {
            v00 = 1.0f / (1.0f + expf(-v00)); v10 = 1.0f / (1.0f + expf(-v10));
            v01 = 1.0f / (1.0f + expf(-v01)); v11 = 1.0f / (1.0f + expf(-v11));
        }
        // oc = 2q
        *(float2*)(gb + (size_t)(2 * q) * TT * HWSZ)     = make_float2(v00, v01);
        // oc = 2q+1
        *(float2*)(gb + (size_t)(2 * q + 1) * TT * HWSZ) = make_float2(v10, v11);
    }
}

__global__ __launch_bounds__(256)
void sru_scan_kernel(float* __restrict__ out)
{
    const int tid = blockIdx.x * blockDim.x + threadIdx.x;   // over B*CG*HW
    const int hw = tid & (HWSZ - 1);
    const int bc = tid >> 14;        // HWSZ = 16384 = 2^14
    const int c  = bc & 15;
    const int b  = bc >> 4;

    const size_t GSZ  = (size_t)BB * CG * TT * HWSZ;
    const size_t base = (((size_t)b * CG + c) * TT) * HWSZ + hw;

    const float* WX  = g_gates + 0 * GSZ + base;
    const float* FT  = g_gates + 1 * GSZ + base;
    const float* FT2 = g_gates + 2 * GSZ + base;
    const float* RT  = g_gates + 3 * GSZ + base;
    const float* RT2 = g_gates + 4 * GSZ + base;
    const float* XX  = g_gates + 5 * GSZ + base;
    float* o = out + base;

    float htl[TT];
    // forward pass (ft, rt):  C0 = 1 - f0
    {
        float f = FT[0];
        float C = 1.0f - f;
        float r = RT[0];
        htl[0] = r * C + (1.0f - r) * XX[0];
#pragma unroll
        for (int t = 1; t < TT; t++) {
            size_t idx = (size_t)t * HWSZ;
            f = FT[idx];
            C = f * C + (1.0f - f) * WX[idx];
            float r2 = RT[idx];
            htl[t] = r2 * C + (1.0f - r2) * XX[idx];
        }
    }
    // backward pass (ft2, rt2), fused add + store
    {
        size_t idx = (size_t)(TT - 1) * HWSZ;
        float f = FT2[idx];
        float C = 1.0f - f;
        float r = RT2[idx];
        o[idx] = htl[TT - 1] + r * C + (1.0f - r) * XX[idx];
#pragma unroll
        for (int t = TT - 2; t >= 0; t--) {
            idx = (size_t)t * HWSZ;
            f = FT2[idx];
            C = f * C + (1.0f - f) * WX[idx];
            float r2 = RT2[idx];
            o[idx] = htl[t] + r2 * C + (1.0f - r2) * XX[idx];
        }
    }
}

extern "C" void kernel_launch(void* const* d_in, const int* in_sizes, int n_in,
                              void* d_out, int out_size)
{
    const float* x  = (const float*)d_in[0];   // [2,16,31,128,128]
    const float* cw = (const float*)d_in[1];   // [96,16,3,3,3]
    const float* cb = (const float*)d_in[2];   // [96]
    float* out = (float*)d_out;                // [2,16,31,128,128]

    dim3 blk(TX, TY, 1);
    dim3 grd(WW / BW, HH / BH, BB * NG * TT);
    conv_gates_kernel<<<grd, blk>>>(x, cw, cb);

    int n = BB * CG * HWSZ;                    // 524288 threads
    sru_scan_kernel<<<n / 256, 256>>>(out);
}

// round 5
// speedup vs baseline: 2.9023x; 2.9023x over previous
#include <cuda_runtime.h>
#include <math.h>
#include <stdint.h>

#define BB   2
#define CIN  16
#define NG   6
#define CG   16
#define NOC  96
#define TT   31
#define HH   128
#define WW   128
#define HWSZ (HH*WW)

// CTA pixel tile: 16h x 16w = 256 px
#define PH   16
#define PW   16
#define MPX  256
#define NTHR 384            // 12 warps: 4 m-tiles (64px) x 3 n-tiles (32oc)

// smem layout (dynamic):
//   xt  [3][18][18][20]  floats  at 0        (77760 B)
//   B9  [9][16][104]     floats  at 77760    (59904 B)
//   (epilogue reuse: Cst[96][260] floats at 0, 99840 B)
#define CIP      20
#define XT_BYTES (3*18*18*CIP*4)        // 77760
#define BNP      104
#define B9_OFF   XT_BYTES
#define B9_BYTES (9*16*BNP*4)           // 59904
#define SMEM_DYN (XT_BYTES + B9_BYTES)  // 137664
#define CPXP     260                    // Cst px-stride (pad, mult of 4)

// gates scratch [g][b][c][t][h][w]
__device__ float g_gates[(size_t)NG * BB * CG * TT * HWSZ];
// tf32-rounded transposed weights [j=27][ci=16][oc=96]
__device__ __align__(16) float g_wT[27 * CIN * NOC];

// ---------------- helpers ----------------
__device__ __forceinline__ uint32_t tf32r(float v) {
    uint32_t r;
    asm("cvt.rna.tf32.f32 %0, %1;" : "=r"(r) : "f"(v));
    return r;
}
__device__ __forceinline__ float ex2f(float z) {
    float r; asm("ex2.approx.f32 %0, %1;" : "=f"(r) : "f"(z)); return r;
}
__device__ __forceinline__ float rcpn(float d) {        // rcp + 1 Newton step
    float r; asm("rcp.approx.f32 %0, %1;" : "=f"(r) : "f"(d));
    return r * fmaf(-d, r, 2.0f);
}
__device__ __forceinline__ float sigf(float v) {
    v = fminf(fmaxf(v, -80.f), 80.f);
    return rcpn(1.0f + ex2f(-1.442695041f * v));
}
__device__ __forceinline__ float tanhfst(float v) {
    v = fminf(fmaxf(v, -40.f), 40.f);
    return fmaf(2.0f, rcpn(1.0f + ex2f(-2.885390082f * v)), -1.0f);
}

// m16n8k8 tf32 mma: a0:(r,k) a1:(r+8,k) a2:(r,k+4) a3:(r+8,k+4)
//                   b0:(k,n) b1:(k+4,n);  c0:(r,2q) c1:(r,2q+1) c2/c3: r+8
#define MMA_TF32(c, a0, a1, a2, a3, b0, b1)                                   \
    asm volatile("mma.sync.aligned.m16n8k8.row.col.f32.tf32.tf32.f32 "        \
                 "{%0,%1,%2,%3}, {%4,%5,%6,%7}, {%8,%9}, {%0,%1,%2,%3};"      \
                 : "+f"((c)[0]), "+f"((c)[1]), "+f"((c)[2]), "+f"((c)[3])     \
                 : "r"(a0), "r"(a1), "r"(a2), "r"(a3), "r"(b0), "r"(b1))

// ---------------- weight prep: transpose + tf32 round ----------------
__global__ void prep_w(const float* __restrict__ cw)
{
    int i = blockIdx.x * 256 + threadIdx.x;           // [0, 27*16*96)
    if (i >= 27 * CIN * NOC) return;
    int oc = i % NOC;
    int ci = (i / NOC) % CIN;
    int j  = i / (NOC * CIN);
    g_wT[i] = __uint_as_float(tf32r(cw[(oc * CIN + ci) * 27 + j]));
}

// ---------------- conv via mma.sync tf32, 27 shifted GEMMs ----------------
__global__ __launch_bounds__(NTHR)
void conv_mma(const float* __restrict__ x, const float* __restrict__ cb)
{
    extern __shared__ __align__(16) char dsm[];
    __shared__ float cbs[NOC];

    const int tid = threadIdx.x;
    const int wid = tid >> 5;
    const int lid = tid & 31;
    const int wm  = wid & 3;          // m-tile (64 px)
    const int wn  = wid >> 2;         // n-tile (32 oc), 0..2

    const int w0 = blockIdx.x * PW;
    const int h0 = blockIdx.y * PH;
    const int zz = blockIdx.z;
    const int t = zz % TT, b = zz / TT;

    if (tid < NOC) cbs[tid] = __ldg(&cb[tid]);

    // ---- stage xt[3][18][18][20] (tf32-rounded, zero-padded halo) ----
    {
        const float* xb = x + (size_t)b * CIN * TT * HWSZ;
        for (int i = tid; i < 3 * 18 * 18 * CIN; i += NTHR) {
            int iw = i % 18;
            int r  = i / 18;
            int ci = r & 15;
            r >>= 4;
            int ih = r % 18;
            int dt = r / 18;
            int tg = t - 1 + dt, hh = h0 - 1 + ih, ww = w0 - 1 + iw;
            float v = 0.0f;
            if ((unsigned)tg < TT && (unsigned)hh < HH && (unsigned)ww < WW)
                v = xb[((size_t)ci * TT + tg) * HWSZ + hh * WW + ww];
            *(uint32_t*)(dsm + ((((dt * 18 + ih) * 18 + iw) * CIP + ci) << 2))
                = tf32r(v);
        }
    }

    // ---- C fragments: c[mb][nf][4], init with bias ----
    float c[4][4][4];
    {
        const int ocb = wn * 32 + (lid & 3) * 2;
#pragma unroll
        for (int mb = 0; mb < 4; mb++)
#pragma unroll
            for (int nf = 0; nf < 4; nf++) {
                float b0v = cbs[ocb + nf * 8];
                float b1v = cbs[ocb + nf * 8 + 1];
                c[mb][nf][0] = b0v; c[mb][nf][1] = b1v;
                c[mb][nf][2] = b0v; c[mb][nf][3] = b1v;
            }
    }

    const int laneA = (lid >> 2) * (CIP * 4) + (lid & 3) * 4;
    const int laneB = (lid & 3) * (BNP * 4) + (lid >> 2) * 4;
    const int hrow  = wm * 4;

    for (int dt = 0; dt < 3; dt++) {
        __syncthreads();   // xt staged (dt=0) / all warps done with prev B9
        // stage B9[9][16][104] for this dt (float4 copies)
        {
            const float4* src = (const float4*)g_wT;
            for (int i = tid; i < 9 * 16 * (NOC / 4); i += NTHR) {
                int row = i / (NOC / 4);          // j9*16 + k
                int n4  = i % (NOC / 4);
                float4 v = src[(dt * 144 + row) * (NOC / 4) + n4];
                *(float4*)(dsm + B9_OFF + ((row * (BNP / 4) + n4) << 4)) = v;
            }
        }
        __syncthreads();

#pragma unroll
        for (int dh = 0; dh < 3; dh++)
#pragma unroll
            for (int dw = 0; dw < 3; dw++) {
                const int j9 = dh * 3 + dw;
#pragma unroll
                for (int ks = 0; ks < 2; ks++) {
                    // B fragments (32 oc = 4 n-frags)
                    uint32_t b0[4], b1[4];
                    const int bb = B9_OFF + (j9 * 16 + ks * 8) * (BNP * 4)
                                 + wn * 128 + laneB;
#pragma unroll
                    for (int nf = 0; nf < 4; nf++) {
                        b0[nf] = *(const uint32_t*)(dsm + bb + nf * 32);
                        b1[nf] = *(const uint32_t*)(dsm + bb + nf * 32
                                                    + 4 * (BNP * 4));
                    }
#pragma unroll
                    for (int mb = 0; mb < 4; mb++) {
                        const int aa = ((dt * 18 + hrow + mb + dh) * 18 + dw)
                                       * (CIP * 4) + ks * 32 + laneA;
                        uint32_t a0 = *(const uint32_t*)(dsm + aa);
                        uint32_t a1 = *(const uint32_t*)(dsm + aa + 8 * CIP * 4);
                        uint32_t a2 = *(const uint32_t*)(dsm + aa + 16);
                        uint32_t a3 = *(const uint32_t*)(dsm + aa + 8 * CIP * 4 + 16);
#pragma unroll
                        for (int nf = 0; nf < 4; nf++)
                            MMA_TF32(c[mb][nf], a0, a1, a2, a3, b0[nf], b1[nf]);
                    }
                }
            }
    }

    // ---- epilogue: activate, transpose via smem, coalesced store ----
    __syncthreads();           // done reading xt/B9; reuse smem as Cst[96][260]
    {
        float* Cs = (float*)dsm;
        const int r = lid >> 2;
#pragma unroll
        for (int mb = 0; mb < 4; mb++) {
            const int px = wm * 64 + mb * 16 + r;
#pragma unroll
            for (int nf = 0; nf < 4; nf++) {
                const int oc0 = wn * 32 + nf * 8 + (lid & 3) * 2;
                const int g = oc0 >> 4;
                const bool th = (g == 0) || (g == 5);
                float v0 = c[mb][nf][0], v1 = c[mb][nf][1];
                float v2 = c[mb][nf][2], v3 = c[mb][nf][3];
                v0 = th ? tanhfst(v0) : sigf(v0);
                v1 = th ? tanhfst(v1) : sigf(v1);
                v2 = th ? tanhfst(v2) : sigf(v2);
                v3 = th ? tanhfst(v3) : sigf(v3);
                Cs[oc0 * CPXP + px]           = v0;
                Cs[(oc0 + 1) * CPXP + px]     = v1;
                Cs[oc0 * CPXP + px + 8]       = v2;
                Cs[(oc0 + 1) * CPXP + px + 8] = v3;
            }
        }
    }
    __syncthreads();
    {
        const float* Cs = (const float*)dsm;
        const size_t tbase = (size_t)t * HWSZ;
#pragma unroll
        for (int it = 0; it < 16; it++) {
            int idx = it * NTHR + tid;          // < 6144
            int oc  = idx >> 6;
            int px4 = idx & 63;
            float4 v = *(const float4*)(Cs + oc * CPXP + px4 * 4);
            int px = px4 * 4;
            int hw = (h0 + (px >> 4)) * WW + w0 + (px & 15);
            int g = oc >> 4, cc = oc & 15;
            *(float4*)(g_gates + ((size_t)(g * BB + b) * CG + cc) * (TT * HWSZ)
                       + tbase + hw) = v;
        }
    }
}

// ---------------- SRU scan (HBM-bound @80%, unchanged) ----------------
__global__ __launch_bounds__(256)
void sru_scan_kernel(float* __restrict__ out)
{
    const int tid = blockIdx.x * blockDim.x + threadIdx.x;
    const int hw = tid & (HWSZ - 1);
    const int bc = tid >> 14;
    const int c  = bc & 15;
    const int b  = bc >> 4;

    const size_t GSZ  = (size_t)BB * CG * TT * HWSZ;
    const size_t base = (((size_t)b * CG + c) * TT) * HWSZ + hw;

    const float* WX  = g_gates + 0 * GSZ + base;
    const float* FT  = g_gates + 1 * GSZ + base;
    const float* FT2 = g_gates + 2 * GSZ + base;
    const float* RT  = g_gates + 3 * GSZ + base;
    const float* RT2 = g_gates + 4 * GSZ + base;
    const float* XX  = g_gates + 5 * GSZ + base;
    float* o = out + base;

    float htl[TT];
    {
        float f = FT[0];
        float C = 1.0f - f;
        float r = RT[0];
        htl[0] = r * C + (1.0f - r) * XX[0];
#pragma unroll
        for (int t = 1; t < TT; t++) {
            size_t idx = (size_t)t * HWSZ;
            f = FT[idx];
            C = f * C + (1.0f - f) * WX[idx];
            float r2 = RT[idx];
            htl[t] = r2 * C + (1.0f - r2) * XX[idx];
        }
    }
    {
        size_t idx = (size_t)(TT - 1) * HWSZ;
        float f = FT2[idx];
        float C = 1.0f - f;
        float r = RT2[idx];
        o[idx] = htl[TT - 1] + r * C + (1.0f - r) * XX[idx];
#pragma unroll
        for (int t = TT - 2; t >= 0; t--) {
            idx = (size_t)t * HWSZ;
            f = FT2[idx];
            C = f * C + (1.0f - f) * WX[idx];
            float r2 = RT2[idx];
            o[idx] = htl[t] + r2 * C + (1.0f - r2) * XX[idx];
        }
    }
}

extern "C" void kernel_launch(void* const* d_in, const int* in_sizes, int n_in,
                              void* d_out, int out_size)
{
    const float* x  = (const float*)d_in[0];   // [2,16,31,128,128]
    const float* cw = (const float*)d_in[1];   // [96,16,3,3,3]
    const float* cb = (const float*)d_in[2];   // [96]
    float* out = (float*)d_out;

    cudaFuncSetAttribute(conv_mma, cudaFuncAttributeMaxDynamicSharedMemorySize,
                         SMEM_DYN);

    prep_w<<<(27 * CIN * NOC + 255) / 256, 256>>>(cw);

    dim3 grd(WW / PW, HH / PH, BB * TT);       // (8, 8, 62) = 3968 CTAs
    conv_mma<<<grd, NTHR, SMEM_DYN>>>(x, cb);

    int n = BB * CG * HWSZ;
    sru_scan_kernel<<<n / 256, 256>>>(out);
}

// round 6
// speedup vs baseline: 3.7192x; 1.2815x over previous
#include <cuda_runtime.h>
#include <cuda_fp16.h>
#include <math.h>
#include <stdint.h>

#define BB   2
#define CIN  16
#define NG   6
#define CG   16
#define NOC  96
#define TT   31
#define HH   128
#define WW   128
#define HWSZ (HH*WW)

// CTA pixel tile: 16h x 16w = 256 px
#define PH   16
#define PW   16
#define NTHR 384            // 12 warps: 4 m-tiles (64px=4h) x 3 n-tiles (32oc)

// smem (halves):
//   xt [3][18][18][24]  at 0       : 3*18*18*24*2 = 46656 B
//   B9 [9][96][24]      at 46656   : 9*96*24*2    = 41472 B
#define CIP      24
#define XT_BYTES (3*18*18*CIP*2)
#define B9_OFF   XT_BYTES
#define B9_BYTES (9*NOC*CIP*2)
#define SMEM_DYN (XT_BYTES + B9_BYTES)   // 88128

// gates scratch [g][b][c][t][h][w]
__device__ float g_gates[(size_t)NG * BB * CG * TT * HWSZ];
// fp16 weights [j=27][oc=96][ci=16]
__device__ __align__(16) __half g_wH[27 * NOC * CIN];

// ---------------- helpers ----------------
__device__ __forceinline__ float ex2f(float z) {
    float r; asm("ex2.approx.f32 %0, %1;" : "=f"(r) : "f"(z)); return r;
}
__device__ __forceinline__ float rcpn(float d) {        // rcp + 1 Newton step
    float r; asm("rcp.approx.f32 %0, %1;" : "=f"(r) : "f"(d));
    return r * fmaf(-d, r, 2.0f);
}
__device__ __forceinline__ float sigf(float v) {
    v = fminf(fmaxf(v, -80.f), 80.f);
    return rcpn(1.0f + ex2f(-1.442695041f * v));
}
__device__ __forceinline__ float tanhfst(float v) {
    v = fminf(fmaxf(v, -40.f), 40.f);
    return fmaf(2.0f, rcpn(1.0f + ex2f(-2.885390082f * v)), -1.0f);
}

// m16n8k16 f16->f32: a0:(r,2c..2c+1) a1:(r+8,..) a2:(r,2c+8..9) a3:(r+8,..)
//                    b0:(2c..2c+1, n) b1:(2c+8..9, n)
//                    c0:(r,2c) c1:(r,2c+1) c2:(r+8,2c) c3:(r+8,2c+1)
#define MMA_F16(c, a0, a1, a2, a3, b0, b1)                                    \
    asm volatile("mma.sync.aligned.m16n8k16.row.col.f32.f16.f16.f32 "         \
                 "{%0,%1,%2,%3}, {%4,%5,%6,%7}, {%8,%9}, {%0,%1,%2,%3};"      \
                 : "+f"((c)[0]), "+f"((c)[1]), "+f"((c)[2]), "+f"((c)[3])     \
                 : "r"(a0), "r"(a1), "r"(a2), "r"(a3), "r"(b0), "r"(b1))

// ---------------- weight prep: [oc][ci][j] f32 -> [j][oc][ci] f16 ----------
__global__ void prep_w(const float* __restrict__ cw)
{
    int i = blockIdx.x * 256 + threadIdx.x;           // [0, 27*96*16)
    if (i >= 27 * NOC * CIN) return;
    int ci = i % CIN;
    int oc = (i / CIN) % NOC;
    int j  = i / (CIN * NOC);
    g_wH[i] = __float2half_rn(cw[(oc * CIN + ci) * 27 + j]);
}

// ---------------- conv via mma.sync fp16, 27 shifted GEMMs ----------------
__global__ __launch_bounds__(NTHR)
void conv_mma(const float* __restrict__ x, const float* __restrict__ cb)
{
    extern __shared__ __align__(16) char dsm[];
    __shared__ float cbs[NOC];

    const int tid = threadIdx.x;
    const int wid = tid >> 5;
    const int lid = tid & 31;
    const int wm  = wid & 3;          // m-tile: 4 h-rows x 16 w = 64 px
    const int wn  = wid >> 2;         // n-tile: 32 oc, 0..2

    const int w0 = blockIdx.x * PW;
    const int h0 = blockIdx.y * PH;
    const int zz = blockIdx.z;
    const int t = zz % TT, b = zz / TT;

    if (tid < NOC) cbs[tid] = __ldg(&cb[tid]);

    // ---- stage xt[3][18][18][24] halves (zero-padded halo) ----
    {
        const float* xb = x + (size_t)b * CIN * TT * HWSZ;
        for (int i = tid; i < 3 * CIN * 18 * 18; i += NTHR) {
            int iw = i % 18;
            int ih = (i / 18) % 18;
            int ci = (i / 324) % CIN;
            int dt = i / (324 * CIN);
            int tg = t - 1 + dt, hh = h0 - 1 + ih, ww = w0 - 1 + iw;
            float v = 0.0f;
            if ((unsigned)tg < TT && (unsigned)hh < HH && (unsigned)ww < WW)
                v = xb[((size_t)ci * TT + tg) * HWSZ + hh * WW + ww];
            *(__half*)(dsm + (((dt * 18 + ih) * 18 + iw) * CIP + ci) * 2)
                = __float2half_rn(v);
        }
    }

    // ---- C fragments: c[mb][nf][4], init with bias ----
    float c[4][4][4];
    {
        const int ocb = wn * 32 + (lid & 3) * 2;
#pragma unroll
        for (int mb = 0; mb < 4; mb++)
#pragma unroll
            for (int nf = 0; nf < 4; nf++) {
                float b0v = cbs[ocb + nf * 8];
                float b1v = cbs[ocb + nf * 8 + 1];
                c[mb][nf][0] = b0v; c[mb][nf][1] = b1v;
                c[mb][nf][2] = b0v; c[mb][nf][3] = b1v;
            }
    }

    // lane offsets (bytes): A row = iw (stride CIP*2=48B), k halves contiguous
    const int laneA = (lid >> 2) * (CIP * 2) + (lid & 3) * 4;
    const int laneB = (lid >> 2) * (CIP * 2) + (lid & 3) * 4;
    const int hrow  = wm * 4;

    for (int dt = 0; dt < 3; dt++) {
        __syncthreads();   // xt staged (dt=0) / prev B9 consumers done
        // stage B9[9][96][24] halves for this dt: rows of 16 halves = 2 float4
        {
            const float4* src = (const float4*)g_wH;
            for (int i = tid; i < 9 * NOC * 2; i += NTHR) {
                int rr = i >> 1;                // j9*96 + oc
                int q  = i & 1;
                float4 v = src[(dt * 9 * NOC + rr) * 2 + q];
                *(float4*)(dsm + B9_OFF + rr * (CIP * 2) + q * 16) = v;
            }
        }
        __syncthreads();

#pragma unroll
        for (int dh = 0; dh < 3; dh++)
#pragma unroll
            for (int dw = 0; dw < 3; dw++) {
                const int j9 = dh * 3 + dw;
                // B fragments: 4 nf, 2 regs each
                uint32_t b0[4], b1[4];
                const int bb = B9_OFF + (j9 * NOC + wn * 32) * (CIP * 2) + laneB;
#pragma unroll
                for (int nf = 0; nf < 4; nf++) {
                    b0[nf] = *(const uint32_t*)(dsm + bb + nf * 8 * (CIP * 2));
                    b1[nf] = *(const uint32_t*)(dsm + bb + nf * 8 * (CIP * 2) + 16);
                }
#pragma unroll
                for (int mb = 0; mb < 4; mb++) {
                    const int aa = ((dt * 18 + hrow + mb + dh) * 18 + dw)
                                   * (CIP * 2) + laneA;
                    uint32_t a0 = *(const uint32_t*)(dsm + aa);
                    uint32_t a1 = *(const uint32_t*)(dsm + aa + 8 * (CIP * 2));
                    uint32_t a2 = *(const uint32_t*)(dsm + aa + 16);
                    uint32_t a3 = *(const uint32_t*)(dsm + aa + 8 * (CIP * 2) + 16);
#pragma unroll
                    for (int nf = 0; nf < 4; nf++)
                        MMA_F16(c[mb][nf], a0, a1, a2, a3, b0[nf], b1[nf]);
                }
            }
    }

    // ---- epilogue: activate + direct store (8w x 4oc lanes => full sectors) --
    {
        const int r   = lid >> 2;               // w within tile (and +8)
        const int wA  = w0 + r;
        const size_t tbase = (size_t)t * HWSZ;
#pragma unroll
        for (int mb = 0; mb < 4; mb++) {
            const int hA = h0 + hrow + mb;
            const size_t rowoff = tbase + (size_t)hA * WW;
#pragma unroll
            for (int nf = 0; nf < 4; nf++) {
                const int oc0 = wn * 32 + nf * 8 + (lid & 3) * 2;
                const int g = oc0 >> 4;
                const bool th = (g == 0) || (g == 5);
                float v0 = c[mb][nf][0], v1 = c[mb][nf][1];
                float v2 = c[mb][nf][2], v3 = c[mb][nf][3];
                v0 = th ? tanhfst(v0) : sigf(v0);
                v1 = th ? tanhfst(v1) : sigf(v1);
                v2 = th ? tanhfst(v2) : sigf(v2);
                v3 = th ? tanhfst(v3) : sigf(v3);
                float* p0 = g_gates + ((size_t)(g * BB + b) * CG + (oc0 & 15))
                            * (TT * HWSZ) + rowoff + wA;
                float* p1 = g_gates + ((size_t)(g * BB + b) * CG + ((oc0 + 1) & 15))
                            * (TT * HWSZ) + rowoff + wA;
                p0[0] = v0;  p1[0] = v1;
                p0[8] = v2;  p1[8] = v3;
            }
        }
    }
}

// ---------------- SRU scan (HBM-bound @80%, unchanged) ----------------
__global__ __launch_bounds__(256)
void sru_scan_kernel(float* __restrict__ out)
{
    const int tid = blockIdx.x * blockDim.x + threadIdx.x;
    const int hw = tid & (HWSZ - 1);
    const int bc = tid >> 14;
    const int c  = bc & 15;
    const int b  = bc >> 4;

    const size_t GSZ  = (size_t)BB * CG * TT * HWSZ;
    const size_t base = (((size_t)b * CG + c) * TT) * HWSZ + hw;

    const float* WX  = g_gates + 0 * GSZ + base;
    const float* FT  = g_gates + 1 * GSZ + base;
    const float* FT2 = g_gates + 2 * GSZ + base;
    const float* RT  = g_gates + 3 * GSZ + base;
    const float* RT2 = g_gates + 4 * GSZ + base;
    const float* XX  = g_gates + 5 * GSZ + base;
    float* o = out + base;

    float htl[TT];
    {
        float f = FT[0];
        float C = 1.0f - f;
        float r = RT[0];
        htl[0] = r * C + (1.0f - r) * XX[0];
#pragma unroll
        for (int t = 1; t < TT; t++) {
            size_t idx = (size_t)t * HWSZ;
            f = FT[idx];
            C = f * C + (1.0f - f) * WX[idx];
            float r2 = RT[idx];
            htl[t] = r2 * C + (1.0f - r2) * XX[idx];
        }
    }
    {
        size_t idx = (size_t)(TT - 1) * HWSZ;
        float f = FT2[idx];
        float C = 1.0f - f;
        float r = RT2[idx];
        o[idx] = htl[TT - 1] + r * C + (1.0f - r) * XX[idx];
#pragma unroll
        for (int t = TT - 2; t >= 0; t--) {
            idx = (size_t)t * HWSZ;
            f = FT2[idx];
            C = f * C + (1.0f - f) * WX[idx];
            float r2 = RT2[idx];
            o[idx] = htl[t] + r2 * C + (1.0f - r2) * XX[idx];
        }
    }
}

extern "C" void kernel_launch(void* const* d_in, const int* in_sizes, int n_in,
                              void* d_out, int out_size)
{
    const float* x  = (const float*)d_in[0];   // [2,16,31,128,128]
    const float* cw = (const float*)d_in[1];   // [96,16,3,3,3]
    const float* cb = (const float*)d_in[2];   // [96]
    float* out = (float*)d_out;

    cudaFuncSetAttribute(conv_mma, cudaFuncAttributeMaxDynamicSharedMemorySize,
                         SMEM_DYN);

    prep_w<<<(27 * NOC * CIN + 255) / 256, 256>>>(cw);

    dim3 grd(WW / PW, HH / PH, BB * TT);       // (8, 8, 62) = 3968 CTAs
    conv_mma<<<grd, NTHR, SMEM_DYN>>>(x, cb);

    int n = BB * CG * HWSZ;
    sru_scan_kernel<<<n / 256, 256>>>(out);
}